// round 3
// baseline (speedup 1.0000x reference)
#include <cuda_runtime.h>

// ---------------------------------------------------------------------------
// Scratch (static __device__ — no allocations allowed anywhere)
// ---------------------------------------------------------------------------
#define NMAX 100096
#define EMAX_TOT 1703936   // E + N self loops (1.6M + 100k), with headroom
#define HID 64

__device__ __align__(16) float g_h  [NMAX * HID];  // h = X @ W
__device__ __align__(16) float g_agg[NMAX * HID];  // aggregation accumulator
__device__ __align__(16) float g_x1 [NMAX * HID];  // layer output / next input
__device__ __align__(16) float g_als[NMAX];
__device__ __align__(16) float g_ald[NMAX];
__device__ __align__(16) unsigned g_mu[NMAX];      // segment max (encoded uint)
__device__ __align__(16) float g_s  [NMAX];        // segment sum
__device__ __align__(16) float g_w  [EMAX_TOT];    // per-edge e, then exp(e-m)
__device__ __align__(16) float g_pool[256 * HID];
__device__               int   g_cnt [256];

// Order-preserving float <-> uint map (for atomicMax on unsigned).
__device__ __forceinline__ unsigned enc_f(float f) {
    unsigned b = __float_as_uint(f);
    return (b & 0x80000000u) ? ~b : (b | 0x80000000u);
}
__device__ __forceinline__ float dec_f(unsigned u) {
    unsigned b = (u & 0x80000000u) ? (u & 0x7FFFFFFFu) : ~u;
    return __uint_as_float(b);
}

// ---------------------------------------------------------------------------
// GEMM: g_h[N, 64] = X[N, K] @ W[K, 64]
// 256 threads/block, 64x64 output tile, 4x4 register tile per thread.
// Static shared, K tiled in chunks of 64 (33.4 KB) — no attribute calls.
// ---------------------------------------------------------------------------
template <int K, bool FROM_SCRATCH>
__global__ void gemm_kernel(const float* __restrict__ Xin,
                            const float* __restrict__ W, int N) {
    const float* __restrict__ X = FROM_SCRATCH ? (const float*)g_x1 : Xin;
    __shared__ float Ws [64 * 64];   // W chunk  [64 k][64 c]
    __shared__ float XsT[64 * 68];   // X chunk transposed [64 k][64 r] pad 68

    const int tid  = threadIdx.x;
    const int row0 = blockIdx.x * 64;
    const int tx = tid & 15;         // cols 4*tx..4*tx+3
    const int ty = tid >> 4;         // rows 4*ty..4*ty+3
    const int KQ = K / 4;

    float acc[4][4] = {};

    for (int k0 = 0; k0 < K; k0 += 64) {
        for (int i = tid; i < 64 * 16; i += 256) {
            int kk = i / 16, cq = i % 16;
            ((float4*)Ws)[kk * 16 + cq] =
                ((const float4*)W)[(k0 + kk) * 16 + cq];
        }
        for (int i = tid; i < 64 * 16; i += 256) {
            int r  = i / 16;
            int kq = i % 16;
            float4 v = make_float4(0.f, 0.f, 0.f, 0.f);
            int gr = row0 + r;
            if (gr < N) v = ((const float4*)X)[gr * KQ + k0 / 4 + kq];
            XsT[(4 * kq + 0) * 68 + r] = v.x;
            XsT[(4 * kq + 1) * 68 + r] = v.y;
            XsT[(4 * kq + 2) * 68 + r] = v.z;
            XsT[(4 * kq + 3) * 68 + r] = v.w;
        }
        __syncthreads();

#pragma unroll 8
        for (int kk = 0; kk < 64; kk++) {
            float4 xv = *(const float4*)&XsT[kk * 68 + 4 * ty];
            float4 wv = *(const float4*)&Ws [kk * 64 + 4 * tx];
            float xr[4] = {xv.x, xv.y, xv.z, xv.w};
            float wc[4] = {wv.x, wv.y, wv.z, wv.w};
#pragma unroll
            for (int r = 0; r < 4; r++)
#pragma unroll
                for (int c = 0; c < 4; c++)
                    acc[r][c] = fmaf(xr[r], wc[c], acc[r][c]);
        }
        __syncthreads();
    }

#pragma unroll
    for (int r = 0; r < 4; r++) {
        int gr = row0 + 4 * ty + r;
        if (gr < N) {
            float4 o = make_float4(acc[r][0], acc[r][1], acc[r][2], acc[r][3]);
            *(float4*)&g_h[gr * HID + 4 * tx] = o;
        }
    }
}

// ---------------------------------------------------------------------------
// Per-node: al_src/al_dst = h . a; init m (encoded), s. One warp per node.
// ---------------------------------------------------------------------------
__global__ void node_prep(const float* __restrict__ a_src,
                          const float* __restrict__ a_dst, int N) {
    int gid  = blockIdx.x * blockDim.x + threadIdx.x;
    int node = gid >> 5;
    int lane = gid & 31;
    if (node >= N) return;
    float h1 = g_h[node * HID + lane];
    float h2 = g_h[node * HID + lane + 32];
    float vs = h1 * a_src[lane] + h2 * a_src[lane + 32];
    float vd = h1 * a_dst[lane] + h2 * a_dst[lane + 32];
#pragma unroll
    for (int o = 16; o > 0; o >>= 1) {
        vs += __shfl_down_sync(0xFFFFFFFFu, vs, o);
        vd += __shfl_down_sync(0xFFFFFFFFu, vd, o);
    }
    if (lane == 0) {
        g_als[node] = vs;
        g_ald[node] = vd;
        g_mu[node]  = 0u;      // below every encoded float (self-loop fills it)
        g_s[node]   = 0.f;
    }
}

__global__ void zero_agg(int n4) {
    int i = blockIdx.x * blockDim.x + threadIdx.x;
    if (i < n4) ((float4*)g_agg)[i] = make_float4(0.f, 0.f, 0.f, 0.f);
}

// ---------------------------------------------------------------------------
// Edge pass 1: e = leaky_relu(als[src] + ald[dst]); segment max into g_mu[dst]
// ---------------------------------------------------------------------------
__global__ void edge_max(const int* __restrict__ ei, int E, int Etot) {
    int eid = blockIdx.x * blockDim.x + threadIdx.x;
    if (eid >= Etot) return;
    int s, d;
    if (eid < E) { s = ei[eid]; d = ei[E + eid]; }
    else         { s = d = eid - E; }
    float e = g_als[s] + g_ald[d];
    e = (e > 0.f) ? e : 0.2f * e;
    g_w[eid] = e;
    atomicMax(&g_mu[d], enc_f(e));
}

// Edge pass 2: w = exp(e - m[dst]); segment sum into s[dst]
__global__ void edge_exp(const int* __restrict__ ei, int E, int Etot) {
    int eid = blockIdx.x * blockDim.x + threadIdx.x;
    if (eid >= Etot) return;
    int d = (eid < E) ? ei[E + eid] : (eid - E);
    float w = __expf(g_w[eid] - dec_f(g_mu[d]));
    g_w[eid] = w;
    atomicAdd(&g_s[d], w);
}

// Edge pass 3: agg[dst] += h[src] * (w / s[dst]).  One warp per edge,
// each lane handles 2 of the 64 feature columns.
__global__ void edge_scatter(const int* __restrict__ ei, int E, int Etot) {
    long long t = (long long)blockIdx.x * blockDim.x + threadIdx.x;
    int eid  = (int)(t >> 5);
    int lane = (int)(t & 31);
    if (eid >= Etot) return;
    int s, d;
    if (eid < E) { s = ei[eid]; d = ei[E + eid]; }
    else         { s = d = eid - E; }
    float coef = g_w[eid] / g_s[d];
    atomicAdd(&g_agg[d * HID + lane],      g_h[s * HID + lane]      * coef);
    atomicAdd(&g_agg[d * HID + lane + 32], g_h[s * HID + lane + 32] * coef);
}

// out = elu(agg + b) -> g_x1
__global__ void bias_elu(const float* __restrict__ b, int n) {
    int i = blockIdx.x * blockDim.x + threadIdx.x;
    if (i >= n) return;
    float v = g_agg[i] + b[i & (HID - 1)];
    g_x1[i] = (v > 0.f) ? v : expm1f(v);
}

// ---------------------------------------------------------------------------
// Pooling + FC
// ---------------------------------------------------------------------------
__global__ void pool_zero(int G) {
    int i = blockIdx.x * blockDim.x + threadIdx.x;
    if (i < G * HID) g_pool[i] = 0.f;
    if (i < G)       g_cnt[i]  = 0;
}

__global__ void pool_acc(const int* __restrict__ batch, int N) {
    int gid  = blockIdx.x * blockDim.x + threadIdx.x;
    int node = gid >> 5;
    int lane = gid & 31;
    if (node >= N) return;
    int g = batch[node];
    atomicAdd(&g_pool[g * HID + lane],      g_x1[node * HID + lane]);
    atomicAdd(&g_pool[g * HID + lane + 32], g_x1[node * HID + lane + 32]);
    if (lane == 0) atomicAdd(&g_cnt[g], 1);
}

__global__ void final_fc(const float* __restrict__ Wfc,
                         const float* __restrict__ bfc,
                         float* __restrict__ out, int G) {
    int g = blockIdx.x * blockDim.x + threadIdx.x;
    if (g >= G) return;
    float acc = 0.f;
#pragma unroll 8
    for (int c = 0; c < HID; c++)
        acc += g_pool[g * HID + c] * Wfc[c];
    float n = (float)(g_cnt[g] > 0 ? g_cnt[g] : 1);
    out[g] = acc / n + bfc[0];
}

// ---------------------------------------------------------------------------
// Launch
// ---------------------------------------------------------------------------
extern "C" void kernel_launch(void* const* d_in, const int* in_sizes, int n_in,
                              void* d_out, int out_size) {
    const float* x     = (const float*)d_in[0];
    const int*   ei    = (const int*)d_in[1];    // int32 (JAX x64 disabled)
    const int*   batch = (const int*)d_in[2];    // int32
    const float* W1  = (const float*)d_in[3];
    const float* as1 = (const float*)d_in[4];
    const float* ad1 = (const float*)d_in[5];
    const float* b1  = (const float*)d_in[6];
    const float* W2  = (const float*)d_in[7];
    const float* as2 = (const float*)d_in[8];
    const float* ad2 = (const float*)d_in[9];
    const float* b2  = (const float*)d_in[10];
    const float* Wfc = (const float*)d_in[11];
    const float* bfc = (const float*)d_in[12];
    float* out = (float*)d_out;

    const int hid = in_sizes[4];            // 64
    const int IN  = in_sizes[3] / hid;      // 128
    const int N   = in_sizes[0] / IN;       // 100000
    const int E   = in_sizes[1] / 2;        // 1600000
    const int Etot = E + N;
    const int G    = out_size;              // 256

    const int gb     = (N + 63) / 64;
    const int nwarps = (N * 32 + 255) / 256;
    const int nagg4  = N * (HID / 4);
    const int eb     = (Etot + 255) / 256;
    const long long scat_threads = (long long)Etot * 32;
    const int sb = (int)((scat_threads + 255) / 256);
    const int n64b = (N * HID + 255) / 256;

    // ---- layer 1 ----
    gemm_kernel<128, false><<<gb, 256>>>(x, W1, N);
    node_prep<<<nwarps, 256>>>(as1, ad1, N);
    zero_agg<<<(nagg4 + 255) / 256, 256>>>(nagg4);
    edge_max<<<eb, 256>>>(ei, E, Etot);
    edge_exp<<<eb, 256>>>(ei, E, Etot);
    edge_scatter<<<sb, 256>>>(ei, E, Etot);
    bias_elu<<<n64b, 256>>>(b1, N * HID);

    // ---- layer 2 ----
    gemm_kernel<64, true><<<gb, 256>>>(x, W2, N);
    node_prep<<<nwarps, 256>>>(as2, ad2, N);
    zero_agg<<<(nagg4 + 255) / 256, 256>>>(nagg4);
    edge_max<<<eb, 256>>>(ei, E, Etot);
    edge_exp<<<eb, 256>>>(ei, E, Etot);
    edge_scatter<<<sb, 256>>>(ei, E, Etot);
    bias_elu<<<n64b, 256>>>(b2, N * HID);

    // ---- pool + fc ----
    pool_zero<<<(G * HID + 255) / 256, 256>>>(G);
    pool_acc<<<nwarps, 256>>>(batch, N);
    final_fc<<<(G + 255) / 256, 256>>>(Wfc, bfc, out, G);
}

// round 4
// speedup vs baseline: 1.4268x; 1.4268x over previous
#include <cuda_runtime.h>

// ---------------------------------------------------------------------------
// Scratch (static __device__ — no allocations allowed anywhere)
// ---------------------------------------------------------------------------
#define NMAX 100096
#define EMAX_TOT 1703936   // E + N self loops (1.6M + 100k), with headroom
#define HID 64

__device__ __align__(16) float g_h  [NMAX * HID];  // h = X @ W
__device__ __align__(16) float g_agg[NMAX * HID];  // aggregation accumulator
__device__ __align__(16) float g_x1 [NMAX * HID];  // layer output / next input
__device__ __align__(16) float g_als[NMAX];
__device__ __align__(16) float g_ald[NMAX];
__device__ __align__(16) unsigned g_mu[NMAX];      // segment max (encoded uint)
__device__ __align__(16) float g_s  [NMAX];        // segment sum
__device__ __align__(16) float g_w  [EMAX_TOT];    // per-edge e, then exp(e-m)
__device__ __align__(16) float g_pool[256 * HID];
__device__               int   g_cnt [256];

// Order-preserving float <-> uint map (for atomicMax on unsigned).
__device__ __forceinline__ unsigned enc_f(float f) {
    unsigned b = __float_as_uint(f);
    return (b & 0x80000000u) ? ~b : (b | 0x80000000u);
}
__device__ __forceinline__ float dec_f(unsigned u) {
    unsigned b = (u & 0x80000000u) ? (u & 0x7FFFFFFFu) : ~u;
    return __uint_as_float(b);
}

// Vector float reduction (sm_90+): 1 instruction adds 4 floats.
__device__ __forceinline__ void red_add_v4(float* addr, float4 v) {
    asm volatile("red.global.add.v4.f32 [%0], {%1, %2, %3, %4};"
                 :: "l"(addr), "f"(v.x), "f"(v.y), "f"(v.z), "f"(v.w)
                 : "memory");
}

// ---------------------------------------------------------------------------
// GEMM: g_h[N, 64] = X[N, K] @ W[K, 64]
// 256 threads/block, 64x64 output tile, 4x4 register tile per thread.
// Static shared, K tiled in chunks of 64 (33.4 KB) — no attribute calls.
// ---------------------------------------------------------------------------
template <int K, bool FROM_SCRATCH>
__global__ void gemm_kernel(const float* __restrict__ Xin,
                            const float* __restrict__ W, int N) {
    const float* __restrict__ X = FROM_SCRATCH ? (const float*)g_x1 : Xin;
    __shared__ float Ws [64 * 64];   // W chunk  [64 k][64 c]
    __shared__ float XsT[64 * 68];   // X chunk transposed [64 k][64 r] pad 68

    const int tid  = threadIdx.x;
    const int row0 = blockIdx.x * 64;
    const int tx = tid & 15;         // cols 4*tx..4*tx+3
    const int ty = tid >> 4;         // rows 4*ty..4*ty+3
    const int KQ = K / 4;

    float acc[4][4] = {};

    for (int k0 = 0; k0 < K; k0 += 64) {
        for (int i = tid; i < 64 * 16; i += 256) {
            int kk = i / 16, cq = i % 16;
            ((float4*)Ws)[kk * 16 + cq] =
                ((const float4*)W)[(k0 + kk) * 16 + cq];
        }
        for (int i = tid; i < 64 * 16; i += 256) {
            int r  = i / 16;
            int kq = i % 16;
            float4 v = make_float4(0.f, 0.f, 0.f, 0.f);
            int gr = row0 + r;
            if (gr < N) v = ((const float4*)X)[gr * KQ + k0 / 4 + kq];
            XsT[(4 * kq + 0) * 68 + r] = v.x;
            XsT[(4 * kq + 1) * 68 + r] = v.y;
            XsT[(4 * kq + 2) * 68 + r] = v.z;
            XsT[(4 * kq + 3) * 68 + r] = v.w;
        }
        __syncthreads();

#pragma unroll 8
        for (int kk = 0; kk < 64; kk++) {
            float4 xv = *(const float4*)&XsT[kk * 68 + 4 * ty];
            float4 wv = *(const float4*)&Ws [kk * 64 + 4 * tx];
            float xr[4] = {xv.x, xv.y, xv.z, xv.w};
            float wc[4] = {wv.x, wv.y, wv.z, wv.w};
#pragma unroll
            for (int r = 0; r < 4; r++)
#pragma unroll
                for (int c = 0; c < 4; c++)
                    acc[r][c] = fmaf(xr[r], wc[c], acc[r][c]);
        }
        __syncthreads();
    }

#pragma unroll
    for (int r = 0; r < 4; r++) {
        int gr = row0 + 4 * ty + r;
        if (gr < N) {
            float4 o = make_float4(acc[r][0], acc[r][1], acc[r][2], acc[r][3]);
            *(float4*)&g_h[gr * HID + 4 * tx] = o;
        }
    }
}

// ---------------------------------------------------------------------------
// Per-node: al_src/al_dst = h . a; init m (encoded), s. One warp per node.
// ---------------------------------------------------------------------------
__global__ void node_prep(const float* __restrict__ a_src,
                          const float* __restrict__ a_dst, int N) {
    int gid  = blockIdx.x * blockDim.x + threadIdx.x;
    int node = gid >> 5;
    int lane = gid & 31;
    if (node >= N) return;
    float h1 = g_h[node * HID + lane];
    float h2 = g_h[node * HID + lane + 32];
    float vs = h1 * a_src[lane] + h2 * a_src[lane + 32];
    float vd = h1 * a_dst[lane] + h2 * a_dst[lane + 32];
#pragma unroll
    for (int o = 16; o > 0; o >>= 1) {
        vs += __shfl_down_sync(0xFFFFFFFFu, vs, o);
        vd += __shfl_down_sync(0xFFFFFFFFu, vd, o);
    }
    if (lane == 0) {
        g_als[node] = vs;
        g_ald[node] = vd;
        g_mu[node]  = 0u;      // below every encoded float (self-loop fills it)
        g_s[node]   = 0.f;
    }
}

__global__ void zero_agg(int n4) {
    int i = blockIdx.x * blockDim.x + threadIdx.x;
    if (i < n4) ((float4*)g_agg)[i] = make_float4(0.f, 0.f, 0.f, 0.f);
}

// ---------------------------------------------------------------------------
// Edge pass 1: e = leaky_relu(als[src] + ald[dst]); segment max into g_mu[dst]
// ---------------------------------------------------------------------------
__global__ void edge_max(const int* __restrict__ ei, int E, int Etot) {
    int eid = blockIdx.x * blockDim.x + threadIdx.x;
    if (eid >= Etot) return;
    int s, d;
    if (eid < E) { s = ei[eid]; d = ei[E + eid]; }
    else         { s = d = eid - E; }
    float e = g_als[s] + g_ald[d];
    e = (e > 0.f) ? e : 0.2f * e;
    g_w[eid] = e;
    atomicMax(&g_mu[d], enc_f(e));
}

// Edge pass 2: w = exp(e - m[dst]); segment sum into s[dst]
__global__ void edge_exp(const int* __restrict__ ei, int E, int Etot) {
    int eid = blockIdx.x * blockDim.x + threadIdx.x;
    if (eid >= Etot) return;
    int d = (eid < E) ? ei[E + eid] : (eid - E);
    float w = __expf(g_w[eid] - dec_f(g_mu[d]));
    g_w[eid] = w;
    atomicAdd(&g_s[d], w);
}

// Edge pass 3: agg[dst] += h[src] * (w / s[dst]).
// 16 lanes per edge; each lane: one float4 gather + one red.global.v4.f32.
__global__ void edge_scatter(const int* __restrict__ ei, int E, int Etot) {
    long long t = (long long)blockIdx.x * blockDim.x + threadIdx.x;
    int eid = (int)(t >> 4);
    int sl  = (int)(t & 15);
    if (eid >= Etot) return;
    int s, d;
    if (eid < E) { s = ei[eid]; d = ei[E + eid]; }
    else         { s = d = eid - E; }
    float coef = g_w[eid] / g_s[d];
    float4 v = *(const float4*)&g_h[s * HID + sl * 4];
    v.x *= coef; v.y *= coef; v.z *= coef; v.w *= coef;
    red_add_v4(&g_agg[d * HID + sl * 4], v);
}

// out = elu(agg + b) -> g_x1
__global__ void bias_elu(const float* __restrict__ b, int n) {
    int i = blockIdx.x * blockDim.x + threadIdx.x;
    if (i >= n) return;
    float v = g_agg[i] + b[i & (HID - 1)];
    g_x1[i] = (v > 0.f) ? v : expm1f(v);
}

// ---------------------------------------------------------------------------
// Pooling + FC
// ---------------------------------------------------------------------------
__global__ void pool_zero(int G) {
    int i = blockIdx.x * blockDim.x + threadIdx.x;
    if (i < G * HID) g_pool[i] = 0.f;
    if (i < G)       g_cnt[i]  = 0;
}

__global__ void pool_acc(const int* __restrict__ batch, int N) {
    int gid  = blockIdx.x * blockDim.x + threadIdx.x;
    int node = gid >> 4;
    int sl   = gid & 15;
    if (node >= N) return;
    int g = batch[node];
    float4 v = *(const float4*)&g_x1[node * HID + sl * 4];
    red_add_v4(&g_pool[g * HID + sl * 4], v);
    if (sl == 0) atomicAdd(&g_cnt[g], 1);
}

__global__ void final_fc(const float* __restrict__ Wfc,
                         const float* __restrict__ bfc,
                         float* __restrict__ out, int G) {
    int g = blockIdx.x * blockDim.x + threadIdx.x;
    if (g >= G) return;
    float acc = 0.f;
#pragma unroll 8
    for (int c = 0; c < HID; c++)
        acc += g_pool[g * HID + c] * Wfc[c];
    float n = (float)(g_cnt[g] > 0 ? g_cnt[g] : 1);
    out[g] = acc / n + bfc[0];
}

// ---------------------------------------------------------------------------
// Launch
// ---------------------------------------------------------------------------
extern "C" void kernel_launch(void* const* d_in, const int* in_sizes, int n_in,
                              void* d_out, int out_size) {
    const float* x     = (const float*)d_in[0];
    const int*   ei    = (const int*)d_in[1];    // int32 (JAX x64 disabled)
    const int*   batch = (const int*)d_in[2];    // int32
    const float* W1  = (const float*)d_in[3];
    const float* as1 = (const float*)d_in[4];
    const float* ad1 = (const float*)d_in[5];
    const float* b1  = (const float*)d_in[6];
    const float* W2  = (const float*)d_in[7];
    const float* as2 = (const float*)d_in[8];
    const float* ad2 = (const float*)d_in[9];
    const float* b2  = (const float*)d_in[10];
    const float* Wfc = (const float*)d_in[11];
    const float* bfc = (const float*)d_in[12];
    float* out = (float*)d_out;

    const int hid = in_sizes[4];            // 64
    const int IN  = in_sizes[3] / hid;      // 128
    const int N   = in_sizes[0] / IN;       // 100000
    const int E   = in_sizes[1] / 2;        // 1600000
    const int Etot = E + N;
    const int G    = out_size;              // 256

    const int gb     = (N + 63) / 64;
    const int nwarps = (N * 32 + 255) / 256;
    const int npool  = (N * 16 + 255) / 256;
    const int nagg4  = N * (HID / 4);
    const int eb     = (Etot + 255) / 256;
    const long long scat_threads = (long long)Etot * 16;
    const int sb = (int)((scat_threads + 255) / 256);
    const int n64b = (N * HID + 255) / 256;

    // ---- layer 1 ----
    gemm_kernel<128, false><<<gb, 256>>>(x, W1, N);
    node_prep<<<nwarps, 256>>>(as1, ad1, N);
    zero_agg<<<(nagg4 + 255) / 256, 256>>>(nagg4);
    edge_max<<<eb, 256>>>(ei, E, Etot);
    edge_exp<<<eb, 256>>>(ei, E, Etot);
    edge_scatter<<<sb, 256>>>(ei, E, Etot);
    bias_elu<<<n64b, 256>>>(b1, N * HID);

    // ---- layer 2 ----
    gemm_kernel<64, true><<<gb, 256>>>(x, W2, N);
    node_prep<<<nwarps, 256>>>(as2, ad2, N);
    zero_agg<<<(nagg4 + 255) / 256, 256>>>(nagg4);
    edge_max<<<eb, 256>>>(ei, E, Etot);
    edge_exp<<<eb, 256>>>(ei, E, Etot);
    edge_scatter<<<sb, 256>>>(ei, E, Etot);
    bias_elu<<<n64b, 256>>>(b2, N * HID);

    // ---- pool + fc ----
    pool_zero<<<(G * HID + 255) / 256, 256>>>(G);
    pool_acc<<<npool, 256>>>(batch, N);
    final_fc<<<(G + 255) / 256, 256>>>(Wfc, bfc, out, G);
}

// round 5
// speedup vs baseline: 2.1496x; 1.5066x over previous
#include <cuda_runtime.h>

// ---------------------------------------------------------------------------
// Scratch (static __device__ — no allocations allowed anywhere)
// ---------------------------------------------------------------------------
#define NMAX   100096
#define EMAX   1605632      // edges without self loops (1.6M) + headroom
#define HID    64
#define SCAN_B 512          // scan block size (elements per block)

__device__ __align__(16) float  g_h  [NMAX * HID];  // h = X @ W
__device__ __align__(16) float  g_x1 [NMAX * HID];  // layer output / next input
__device__ __align__(16) float  g_als[NMAX];
__device__ __align__(16) float  g_ald[NMAX];
__device__ __align__(16) float  g_w  [EMAX];        // per-edge e (CSR order)
__device__ __align__(16) float2 g_ws [EMAX];        // packed (w, src) per edge
__device__               int    g_deg [NMAX];
__device__               int    g_rptr[NMAX + 1];
__device__               int    g_cur [NMAX];
__device__               int    g_csrc[EMAX];
__device__               int    g_bsum[1024];
__device__               int    g_bscan[1024];
__device__ __align__(16) float  g_pool[256 * HID];
__device__               int    g_cnt [256];

// Vector float reduction (sm_90+)
__device__ __forceinline__ void red_add_v4(float* addr, float4 v) {
    asm volatile("red.global.add.v4.f32 [%0], {%1, %2, %3, %4};"
                 :: "l"(addr), "f"(v.x), "f"(v.y), "f"(v.z), "f"(v.w)
                 : "memory");
}

// ---------------------------------------------------------------------------
// CSR build: degree count -> 3-kernel exclusive scan -> atomic fill
// ---------------------------------------------------------------------------
__global__ void deg_zero(int N) {
    int i = blockIdx.x * blockDim.x + threadIdx.x;
    if (i < N) g_deg[i] = 0;
}

__global__ void deg_count(const int* __restrict__ ei, int E) {
    int e = blockIdx.x * blockDim.x + threadIdx.x;
    if (e < E) atomicAdd(&g_deg[ei[E + e]], 1);
}

__global__ void scan_blocks(int N) {        // block-local exclusive scan
    __shared__ int sd[SCAN_B];
    int tid = threadIdx.x;
    int i = blockIdx.x * SCAN_B + tid;
    int v = (i < N) ? g_deg[i] : 0;
    sd[tid] = v;
    __syncthreads();
#pragma unroll
    for (int off = 1; off < SCAN_B; off <<= 1) {
        int t = (tid >= off) ? sd[tid - off] : 0;
        __syncthreads();
        sd[tid] += t;
        __syncthreads();
    }
    if (i < N) g_rptr[i] = sd[tid] - v;     // exclusive within block
    if (tid == SCAN_B - 1) g_bsum[blockIdx.x] = sd[tid];
}

__global__ void scan_bsum(int nb) {         // single block, 1024 threads
    __shared__ int sd[1024];
    int tid = threadIdx.x;
    int v = (tid < nb) ? g_bsum[tid] : 0;
    sd[tid] = v;
    __syncthreads();
#pragma unroll
    for (int off = 1; off < 1024; off <<= 1) {
        int t = (tid >= off) ? sd[tid - off] : 0;
        __syncthreads();
        sd[tid] += t;
        __syncthreads();
    }
    g_bscan[tid] = sd[tid] - v;
}

__global__ void scan_add(int N, int E) {
    int i = blockIdx.x * blockDim.x + threadIdx.x;
    if (i < N) {
        int r = g_rptr[i] + g_bscan[i / SCAN_B];
        g_rptr[i] = r;
        g_cur[i]  = r;
    }
    if (i == 0) g_rptr[N] = E;
}

__global__ void csr_fill(const int* __restrict__ ei, int E) {
    int e = blockIdx.x * blockDim.x + threadIdx.x;
    if (e >= E) return;
    int s = ei[e], d = ei[E + e];
    int pos = atomicAdd(&g_cur[d], 1);
    g_csrc[pos] = s;
}

// ---------------------------------------------------------------------------
// GEMM: g_h[N, 64] = X[N, K] @ W[K, 64]   (unchanged from R4)
// ---------------------------------------------------------------------------
template <int K, bool FROM_SCRATCH>
__global__ void gemm_kernel(const float* __restrict__ Xin,
                            const float* __restrict__ W, int N) {
    const float* __restrict__ X = FROM_SCRATCH ? (const float*)g_x1 : Xin;
    __shared__ float Ws [64 * 64];
    __shared__ float XsT[64 * 68];

    const int tid  = threadIdx.x;
    const int row0 = blockIdx.x * 64;
    const int tx = tid & 15;
    const int ty = tid >> 4;
    const int KQ = K / 4;

    float acc[4][4] = {};

    for (int k0 = 0; k0 < K; k0 += 64) {
        for (int i = tid; i < 64 * 16; i += 256) {
            int kk = i / 16, cq = i % 16;
            ((float4*)Ws)[kk * 16 + cq] =
                ((const float4*)W)[(k0 + kk) * 16 + cq];
        }
        for (int i = tid; i < 64 * 16; i += 256) {
            int r = i / 16, kq = i % 16;
            float4 v = make_float4(0.f, 0.f, 0.f, 0.f);
            int gr = row0 + r;
            if (gr < N) v = ((const float4*)X)[gr * KQ + k0 / 4 + kq];
            XsT[(4 * kq + 0) * 68 + r] = v.x;
            XsT[(4 * kq + 1) * 68 + r] = v.y;
            XsT[(4 * kq + 2) * 68 + r] = v.z;
            XsT[(4 * kq + 3) * 68 + r] = v.w;
        }
        __syncthreads();

#pragma unroll 8
        for (int kk = 0; kk < 64; kk++) {
            float4 xv = *(const float4*)&XsT[kk * 68 + 4 * ty];
            float4 wv = *(const float4*)&Ws [kk * 64 + 4 * tx];
            float xr[4] = {xv.x, xv.y, xv.z, xv.w};
            float wc[4] = {wv.x, wv.y, wv.z, wv.w};
#pragma unroll
            for (int r = 0; r < 4; r++)
#pragma unroll
                for (int c = 0; c < 4; c++)
                    acc[r][c] = fmaf(xr[r], wc[c], acc[r][c]);
        }
        __syncthreads();
    }

#pragma unroll
    for (int r = 0; r < 4; r++) {
        int gr = row0 + 4 * ty + r;
        if (gr < N) {
            float4 o = make_float4(acc[r][0], acc[r][1], acc[r][2], acc[r][3]);
            *(float4*)&g_h[gr * HID + 4 * tx] = o;
        }
    }
}

// ---------------------------------------------------------------------------
// Per-node attention logits. One warp per node.
// ---------------------------------------------------------------------------
__global__ void node_prep(const float* __restrict__ a_src,
                          const float* __restrict__ a_dst, int N) {
    int gid  = blockIdx.x * blockDim.x + threadIdx.x;
    int node = gid >> 5;
    int lane = gid & 31;
    if (node >= N) return;
    float h1 = g_h[node * HID + lane];
    float h2 = g_h[node * HID + lane + 32];
    float vs = h1 * a_src[lane] + h2 * a_src[lane + 32];
    float vd = h1 * a_dst[lane] + h2 * a_dst[lane + 32];
#pragma unroll
    for (int o = 16; o > 0; o >>= 1) {
        vs += __shfl_down_sync(0xFFFFFFFFu, vs, o);
        vd += __shfl_down_sync(0xFFFFFFFFu, vd, o);
    }
    if (lane == 0) {
        g_als[node] = vs;
        g_ald[node] = vd;
    }
}

// ---------------------------------------------------------------------------
// Fused GAT aggregation over CSR. One warp per dst node:
//   max -> exp/sum -> weighted accumulate -> /sum + bias + ELU -> g_x1
// Self-loop handled analytically.
// ---------------------------------------------------------------------------
__global__ void gat_csr(const float* __restrict__ b, int N) {
    int gid  = blockIdx.x * blockDim.x + threadIdx.x;
    int node = gid >> 5;
    int lane = gid & 31;
    if (node >= N) return;

    int row0 = g_rptr[node];
    int deg  = g_rptr[node + 1] - row0;

    float ald_d = g_ald[node];
    float e_self = g_als[node] + ald_d;
    e_self = (e_self > 0.f) ? e_self : 0.2f * e_self;

    // pass 1: e per edge, warp max
    float m = e_self;
    for (int j = lane; j < deg; j += 32) {
        int s = g_csrc[row0 + j];
        float e = g_als[s] + ald_d;
        e = (e > 0.f) ? e : 0.2f * e;
        g_w[row0 + j] = e;
        m = fmaxf(m, e);
    }
#pragma unroll
    for (int o = 16; o > 0; o >>= 1)
        m = fmaxf(m, __shfl_xor_sync(0xFFFFFFFFu, m, o));

    // pass 2: w = exp(e - m); sum; pack (w, src)
    float ssum = 0.f;
    for (int j = lane; j < deg; j += 32) {
        float w = __expf(g_w[row0 + j] - m);
        int   s = g_csrc[row0 + j];
        g_ws[row0 + j] = make_float2(w, __int_as_float(s));
        ssum += w;
    }
#pragma unroll
    for (int o = 16; o > 0; o >>= 1)
        ssum += __shfl_xor_sync(0xFFFFFFFFu, ssum, o);
    float w_self = __expf(e_self - m);
    ssum += w_self;
    __syncwarp();   // g_ws visible across the warp

    // pass 3: acc = sum_e w_e * h[src_e]  (float2 per lane, unroll x2)
    float2 hv = *(const float2*)&g_h[node * HID + 2 * lane];
    float2 acc = make_float2(w_self * hv.x, w_self * hv.y);
    int j = 0;
    for (; j + 2 <= deg; j += 2) {
        float2 ws0 = g_ws[row0 + j];
        float2 ws1 = g_ws[row0 + j + 1];
        int s0 = __float_as_int(ws0.y);
        int s1 = __float_as_int(ws1.y);
        float2 h0 = *(const float2*)&g_h[s0 * HID + 2 * lane];
        float2 h1 = *(const float2*)&g_h[s1 * HID + 2 * lane];
        acc.x = fmaf(ws0.x, h0.x, acc.x);
        acc.y = fmaf(ws0.x, h0.y, acc.y);
        acc.x = fmaf(ws1.x, h1.x, acc.x);
        acc.y = fmaf(ws1.x, h1.y, acc.y);
    }
    if (j < deg) {
        float2 ws0 = g_ws[row0 + j];
        int s0 = __float_as_int(ws0.y);
        float2 h0 = *(const float2*)&g_h[s0 * HID + 2 * lane];
        acc.x = fmaf(ws0.x, h0.x, acc.x);
        acc.y = fmaf(ws0.x, h0.y, acc.y);
    }

    float inv = __fdividef(1.f, ssum);
    float2 bb = *(const float2*)&b[2 * lane];
    float vx = acc.x * inv + bb.x;
    float vy = acc.y * inv + bb.y;
    vx = (vx > 0.f) ? vx : expm1f(vx);
    vy = (vy > 0.f) ? vy : expm1f(vy);
    *(float2*)&g_x1[node * HID + 2 * lane] = make_float2(vx, vy);
}

// ---------------------------------------------------------------------------
// Pooling + FC
// ---------------------------------------------------------------------------
__global__ void pool_zero(int G) {
    int i = blockIdx.x * blockDim.x + threadIdx.x;
    if (i < G * HID) g_pool[i] = 0.f;
    if (i < G)       g_cnt[i]  = 0;
}

__global__ void pool_acc(const int* __restrict__ batch, int N) {
    int gid  = blockIdx.x * blockDim.x + threadIdx.x;
    int node = gid >> 4;
    int sl   = gid & 15;
    if (node >= N) return;
    int g = batch[node];
    float4 v = *(const float4*)&g_x1[node * HID + sl * 4];
    red_add_v4(&g_pool[g * HID + sl * 4], v);
    if (sl == 0) atomicAdd(&g_cnt[g], 1);
}

__global__ void final_fc(const float* __restrict__ Wfc,
                         const float* __restrict__ bfc,
                         float* __restrict__ out, int G) {
    int g = blockIdx.x * blockDim.x + threadIdx.x;
    if (g >= G) return;
    float acc = 0.f;
#pragma unroll 8
    for (int c = 0; c < HID; c++)
        acc += g_pool[g * HID + c] * Wfc[c];
    float n = (float)(g_cnt[g] > 0 ? g_cnt[g] : 1);
    out[g] = acc / n + bfc[0];
}

// ---------------------------------------------------------------------------
// Launch
// ---------------------------------------------------------------------------
extern "C" void kernel_launch(void* const* d_in, const int* in_sizes, int n_in,
                              void* d_out, int out_size) {
    const float* x     = (const float*)d_in[0];
    const int*   ei    = (const int*)d_in[1];
    const int*   batch = (const int*)d_in[2];
    const float* W1  = (const float*)d_in[3];
    const float* as1 = (const float*)d_in[4];
    const float* ad1 = (const float*)d_in[5];
    const float* b1  = (const float*)d_in[6];
    const float* W2  = (const float*)d_in[7];
    const float* as2 = (const float*)d_in[8];
    const float* ad2 = (const float*)d_in[9];
    const float* b2  = (const float*)d_in[10];
    const float* Wfc = (const float*)d_in[11];
    const float* bfc = (const float*)d_in[12];
    float* out = (float*)d_out;

    const int hid = in_sizes[4];            // 64
    const int IN  = in_sizes[3] / hid;      // 128
    const int N   = in_sizes[0] / IN;       // 100000
    const int E   = in_sizes[1] / 2;        // 1600000
    const int G   = out_size;               // 256

    const int gb     = (N + 63) / 64;
    const int nwarps = (N * 32 + 255) / 256;
    const int npool  = (N * 16 + 255) / 256;
    const int eb     = (E + 255) / 256;
    const int nb256  = (N + 255) / 256;
    const int nbscan = (N + SCAN_B - 1) / SCAN_B;

    // ---- CSR build (shared by both layers) ----
    deg_zero<<<nb256, 256>>>(N);
    deg_count<<<eb, 256>>>(ei, E);
    scan_blocks<<<nbscan, SCAN_B>>>(N);
    scan_bsum<<<1, 1024>>>(nbscan);
    scan_add<<<nb256, 256>>>(N, E);
    csr_fill<<<eb, 256>>>(ei, E);

    // ---- layer 1 ----
    gemm_kernel<128, false><<<gb, 256>>>(x, W1, N);
    node_prep<<<nwarps, 256>>>(as1, ad1, N);
    gat_csr<<<nwarps, 256>>>(b1, N);

    // ---- layer 2 ----
    gemm_kernel<64, true><<<gb, 256>>>(x, W2, N);
    node_prep<<<nwarps, 256>>>(as2, ad2, N);
    gat_csr<<<nwarps, 256>>>(b2, N);

    // ---- pool + fc ----
    pool_zero<<<(G * HID + 255) / 256, 256>>>(G);
    pool_acc<<<npool, 256>>>(batch, N);
    final_fc<<<(G + 255) / 256, 256>>>(Wfc, bfc, out, G);
}

// round 6
// speedup vs baseline: 2.3644x; 1.0999x over previous
#include <cuda_runtime.h>

// ---------------------------------------------------------------------------
// Scratch (static __device__ — no allocations allowed anywhere)
// ---------------------------------------------------------------------------
#define NMAX   100096
#define EMAX   1605632      // edges without self loops (1.6M) + headroom
#define HID    64

__device__ __align__(16) float  g_h  [NMAX * HID];  // h = X @ W
__device__ __align__(16) float  g_x1 [NMAX * HID];  // layer output / next input
__device__ __align__(16) float  g_als[NMAX];
__device__ __align__(16) float  g_ald[NMAX];
__device__               int    g_deg [NMAX];
__device__               int    g_rptr[NMAX];
__device__               int    g_cur [NMAX];
__device__               int    g_csrc[EMAX];
__device__               int    g_total;
__device__ __align__(16) float  g_pool[256 * HID];
__device__               int    g_cnt [256];

// Vector float reduction (sm_90+)
__device__ __forceinline__ void red_add_v4(float* addr, float4 v) {
    asm volatile("red.global.add.v4.f32 [%0], {%1, %2, %3, %4};"
                 :: "l"(addr), "f"(v.x), "f"(v.y), "f"(v.z), "f"(v.w)
                 : "memory");
}

// ---------------------------------------------------------------------------
// CSR build: degree count -> atomic row allocation -> atomic fill.
// Row order across nodes is arbitrary (atomic allocator); each node's edge
// list is contiguous, which is all gat_csr needs.
// ---------------------------------------------------------------------------
__global__ void deg_zero(int N) {
    int i = blockIdx.x * blockDim.x + threadIdx.x;
    if (i < N) g_deg[i] = 0;
    if (i == 0) g_total = 0;
}

__global__ void deg_count(const int* __restrict__ ei, int E) {
    int e = blockIdx.x * blockDim.x + threadIdx.x;
    if (e < E) atomicAdd(&g_deg[ei[E + e]], 1);
}

__global__ void row_alloc(int N) {
    int i = blockIdx.x * blockDim.x + threadIdx.x;
    if (i >= N) return;
    int d = g_deg[i];
    int r = d ? atomicAdd(&g_total, d) : 0;
    g_rptr[i] = r;
    g_cur[i]  = r;
}

__global__ void csr_fill(const int* __restrict__ ei, int E) {
    int e = blockIdx.x * blockDim.x + threadIdx.x;
    if (e >= E) return;
    int s = ei[e], d = ei[E + e];
    int pos = atomicAdd(&g_cur[d], 1);
    g_csrc[pos] = s;
}

// ---------------------------------------------------------------------------
// GEMM: g_h[N, 64] = X[N, K] @ W[K, 64], with fused attention-logit epilogue:
// g_als = h . a_src, g_ald = h . a_dst (shfl-reduce across the 16 tx lanes).
// ---------------------------------------------------------------------------
template <int K, bool FROM_SCRATCH>
__global__ void gemm_kernel(const float* __restrict__ Xin,
                            const float* __restrict__ W,
                            const float* __restrict__ a_src,
                            const float* __restrict__ a_dst, int N) {
    const float* __restrict__ X = FROM_SCRATCH ? (const float*)g_x1 : Xin;
    __shared__ float Ws [64 * 64];
    __shared__ float XsT[64 * 68];

    const int tid  = threadIdx.x;
    const int row0 = blockIdx.x * 64;
    const int tx = tid & 15;         // cols 4*tx..4*tx+3
    const int ty = tid >> 4;         // rows 4*ty..4*ty+3
    const int KQ = K / 4;

    float acc[4][4] = {};

    for (int k0 = 0; k0 < K; k0 += 64) {
        for (int i = tid; i < 64 * 16; i += 256) {
            int kk = i / 16, cq = i % 16;
            ((float4*)Ws)[kk * 16 + cq] =
                ((const float4*)W)[(k0 + kk) * 16 + cq];
        }
        for (int i = tid; i < 64 * 16; i += 256) {
            int r = i / 16, kq = i % 16;
            float4 v = make_float4(0.f, 0.f, 0.f, 0.f);
            int gr = row0 + r;
            if (gr < N) v = ((const float4*)X)[gr * KQ + k0 / 4 + kq];
            XsT[(4 * kq + 0) * 68 + r] = v.x;
            XsT[(4 * kq + 1) * 68 + r] = v.y;
            XsT[(4 * kq + 2) * 68 + r] = v.z;
            XsT[(4 * kq + 3) * 68 + r] = v.w;
        }
        __syncthreads();

#pragma unroll 8
        for (int kk = 0; kk < 64; kk++) {
            float4 xv = *(const float4*)&XsT[kk * 68 + 4 * ty];
            float4 wv = *(const float4*)&Ws [kk * 64 + 4 * tx];
            float xr[4] = {xv.x, xv.y, xv.z, xv.w};
            float wc[4] = {wv.x, wv.y, wv.z, wv.w};
#pragma unroll
            for (int r = 0; r < 4; r++)
#pragma unroll
                for (int c = 0; c < 4; c++)
                    acc[r][c] = fmaf(xr[r], wc[c], acc[r][c]);
        }
        __syncthreads();
    }

    float4 avs = *(const float4*)&a_src[4 * tx];
    float4 avd = *(const float4*)&a_dst[4 * tx];

#pragma unroll
    for (int r = 0; r < 4; r++) {
        int gr = row0 + 4 * ty + r;
        float ps = acc[r][0] * avs.x + acc[r][1] * avs.y
                 + acc[r][2] * avs.z + acc[r][3] * avs.w;
        float pd = acc[r][0] * avd.x + acc[r][1] * avd.y
                 + acc[r][2] * avd.z + acc[r][3] * avd.w;
#pragma unroll
        for (int o = 8; o > 0; o >>= 1) {     // reduce across the 16 tx lanes
            ps += __shfl_xor_sync(0xFFFFFFFFu, ps, o);
            pd += __shfl_xor_sync(0xFFFFFFFFu, pd, o);
        }
        if (gr < N) {
            float4 o = make_float4(acc[r][0], acc[r][1], acc[r][2], acc[r][3]);
            *(float4*)&g_h[gr * HID + 4 * tx] = o;
            if (tx == 0) {
                g_als[gr] = ps;
                g_ald[gr] = pd;
            }
        }
    }
}

// ---------------------------------------------------------------------------
// Fused single-pass GAT aggregation over CSR. One warp per dst node:
//   per edge: w = exp(leaky_relu(als[src] + ald[dst]))  (no max-sub: softmax
//   is shift-invariant and logits are O(10), far from fp32 overflow)
//   acc[lane cols] += w * h[src];  final: acc/Σw + bias, ELU -> g_x1.
// Self-loop handled analytically.
// ---------------------------------------------------------------------------
__global__ void gat_csr(const float* __restrict__ b, int N) {
    int gid  = blockIdx.x * blockDim.x + threadIdx.x;
    int node = gid >> 5;
    int lane = gid & 31;
    if (node >= N) return;

    int row0 = g_rptr[node];
    int deg  = g_deg[node];

    float ald_d = g_ald[node];
    float e_self = g_als[node] + ald_d;
    e_self = (e_self > 0.f) ? e_self : 0.2f * e_self;
    float w_self = __expf(e_self);

    float2 hv = *(const float2*)&g_h[node * HID + 2 * lane];
    float ax = w_self * hv.x;
    float ay = w_self * hv.y;
    float wpart = 0.f;

    for (int c0 = 0; c0 < deg; c0 += 32) {
        int j = c0 + lane;
        int   s = 0;
        float w = 0.f;
        if (j < deg) {
            s = g_csrc[row0 + j];
            float e = g_als[s] + ald_d;
            e = (e > 0.f) ? e : 0.2f * e;
            w = __expf(e);
        }
        wpart += w;
        int kmax = min(32, deg - c0);
#pragma unroll 4
        for (int k = 0; k < kmax; k++) {
            float wk = __shfl_sync(0xFFFFFFFFu, w, k);
            int   sk = __shfl_sync(0xFFFFFFFFu, s, k);
            float2 hk = *(const float2*)&g_h[sk * HID + 2 * lane];
            ax = fmaf(wk, hk.x, ax);
            ay = fmaf(wk, hk.y, ay);
        }
    }

#pragma unroll
    for (int o = 16; o > 0; o >>= 1)
        wpart += __shfl_xor_sync(0xFFFFFFFFu, wpart, o);
    float inv = __fdividef(1.f, wpart + w_self);

    float2 bb = *(const float2*)&b[2 * lane];
    float vx = ax * inv + bb.x;
    float vy = ay * inv + bb.y;
    vx = (vx > 0.f) ? vx : expm1f(vx);
    vy = (vy > 0.f) ? vy : expm1f(vy);
    *(float2*)&g_x1[node * HID + 2 * lane] = make_float2(vx, vy);
}

// ---------------------------------------------------------------------------
// Pooling + FC
// ---------------------------------------------------------------------------
__global__ void pool_zero(int G) {
    int i = blockIdx.x * blockDim.x + threadIdx.x;
    if (i < G * HID) g_pool[i] = 0.f;
    if (i < G)       g_cnt[i]  = 0;
}

__global__ void pool_acc(const int* __restrict__ batch, int N) {
    int gid  = blockIdx.x * blockDim.x + threadIdx.x;
    int node = gid >> 4;
    int sl   = gid & 15;
    if (node >= N) return;
    int g = batch[node];
    float4 v = *(const float4*)&g_x1[node * HID + sl * 4];
    red_add_v4(&g_pool[g * HID + sl * 4], v);
    if (sl == 0) atomicAdd(&g_cnt[g], 1);
}

__global__ void final_fc(const float* __restrict__ Wfc,
                         const float* __restrict__ bfc,
                         float* __restrict__ out, int G) {
    int g = blockIdx.x * blockDim.x + threadIdx.x;
    if (g >= G) return;
    float acc = 0.f;
#pragma unroll 8
    for (int c = 0; c < HID; c++)
        acc += g_pool[g * HID + c] * Wfc[c];
    float n = (float)(g_cnt[g] > 0 ? g_cnt[g] : 1);
    out[g] = acc / n + bfc[0];
}

// ---------------------------------------------------------------------------
// Launch
// ---------------------------------------------------------------------------
extern "C" void kernel_launch(void* const* d_in, const int* in_sizes, int n_in,
                              void* d_out, int out_size) {
    const float* x     = (const float*)d_in[0];
    const int*   ei    = (const int*)d_in[1];
    const int*   batch = (const int*)d_in[2];
    const float* W1  = (const float*)d_in[3];
    const float* as1 = (const float*)d_in[4];
    const float* ad1 = (const float*)d_in[5];
    const float* b1  = (const float*)d_in[6];
    const float* W2  = (const float*)d_in[7];
    const float* as2 = (const float*)d_in[8];
    const float* ad2 = (const float*)d_in[9];
    const float* b2  = (const float*)d_in[10];
    const float* Wfc = (const float*)d_in[11];
    const float* bfc = (const float*)d_in[12];
    float* out = (float*)d_out;

    const int hid = in_sizes[4];            // 64
    const int IN  = in_sizes[3] / hid;      // 128
    const int N   = in_sizes[0] / IN;       // 100000
    const int E   = in_sizes[1] / 2;        // 1600000
    const int G   = out_size;               // 256

    const int gb     = (N + 63) / 64;
    const int nwarps = (N * 32 + 255) / 256;
    const int npool  = (N * 16 + 255) / 256;
    const int eb     = (E + 255) / 256;
    const int nb256  = (N + 255) / 256;

    // ---- CSR build (shared by both layers) ----
    deg_zero<<<nb256, 256>>>(N);
    deg_count<<<eb, 256>>>(ei, E);
    row_alloc<<<nb256, 256>>>(N);
    csr_fill<<<eb, 256>>>(ei, E);

    // ---- layer 1 ----
    gemm_kernel<128, false><<<gb, 256>>>(x, W1, as1, ad1, N);
    gat_csr<<<nwarps, 256>>>(b1, N);

    // ---- layer 2 ----
    gemm_kernel<64, true><<<gb, 256>>>(x, W2, as2, ad2, N);
    gat_csr<<<nwarps, 256>>>(b2, N);

    // ---- pool + fc ----
    pool_zero<<<(G * HID + 255) / 256, 256>>>(G);
    pool_acc<<<npool, 256>>>(batch, N);
    final_fc<<<(G + 255) / 256, 256>>>(Wfc, bfc, out, G);
}

// round 7
// speedup vs baseline: 2.3879x; 1.0099x over previous
#include <cuda_runtime.h>
#include <cuda_fp16.h>

// ---------------------------------------------------------------------------
// Scratch (static __device__ — no allocations allowed anywhere)
// ---------------------------------------------------------------------------
#define NMAX   100096
#define EMAX   1605632      // edges without self loops (1.6M) + headroom
#define HID    64

__device__ __align__(16) __half g_hh [NMAX * HID];  // h = X @ W (fp16 gather copy)
__device__ __align__(16) float  g_x1 [NMAX * HID];  // layer output / next input
__device__ __align__(16) float  g_als[NMAX];
__device__ __align__(16) float  g_ald[NMAX];
__device__               int    g_deg [NMAX];
__device__               int    g_rptr[NMAX];
__device__               int    g_cur [NMAX];
__device__               int    g_csrc[EMAX];
__device__               int    g_total;
__device__ __align__(16) float  g_pool[256 * HID];
__device__               int    g_cnt [256];

// Vector float reduction (sm_90+)
__device__ __forceinline__ void red_add_v4(float* addr, float4 v) {
    asm volatile("red.global.add.v4.f32 [%0], {%1, %2, %3, %4};"
                 :: "l"(addr), "f"(v.x), "f"(v.y), "f"(v.z), "f"(v.w)
                 : "memory");
}

// ---------------------------------------------------------------------------
// CSR build: degree count -> atomic row allocation -> atomic fill.
// 4 edges per thread (int4 loads) for memory-level parallelism: these
// kernels are latency-bound (issue 4.3% in ncu), not throughput-bound.
// ---------------------------------------------------------------------------
__global__ void deg_zero(int N) {
    int i = blockIdx.x * blockDim.x + threadIdx.x;
    if (i < N) g_deg[i] = 0;
    if (i == 0) g_total = 0;
}

__global__ void deg_count(const int* __restrict__ ei, int E) {
    int t = blockIdx.x * blockDim.x + threadIdx.x;
    int base = 4 * t;
    if (base + 3 < E && ((E & 3) == 0)) {
        int4 d4 = *(const int4*)&ei[E + base];
        atomicAdd(&g_deg[d4.x], 1);
        atomicAdd(&g_deg[d4.y], 1);
        atomicAdd(&g_deg[d4.z], 1);
        atomicAdd(&g_deg[d4.w], 1);
    } else {
        for (int j = base; j < E && j < base + 4; j++)
            atomicAdd(&g_deg[ei[E + j]], 1);
    }
}

__global__ void row_alloc(int N) {
    int i = blockIdx.x * blockDim.x + threadIdx.x;
    if (i >= N) return;
    int d = g_deg[i];
    int r = d ? atomicAdd(&g_total, d) : 0;
    g_rptr[i] = r;
    g_cur[i]  = r;
}

__global__ void csr_fill(const int* __restrict__ ei, int E) {
    int t = blockIdx.x * blockDim.x + threadIdx.x;
    int base = 4 * t;
    if (base + 3 < E && ((E & 3) == 0)) {
        int4 s4 = *(const int4*)&ei[base];
        int4 d4 = *(const int4*)&ei[E + base];
        int p0 = atomicAdd(&g_cur[d4.x], 1);
        int p1 = atomicAdd(&g_cur[d4.y], 1);
        int p2 = atomicAdd(&g_cur[d4.z], 1);
        int p3 = atomicAdd(&g_cur[d4.w], 1);
        g_csrc[p0] = s4.x;
        g_csrc[p1] = s4.y;
        g_csrc[p2] = s4.z;
        g_csrc[p3] = s4.w;
    } else {
        for (int j = base; j < E && j < base + 4; j++) {
            int pos = atomicAdd(&g_cur[ei[E + j]], 1);
            g_csrc[pos] = ei[j];
        }
    }
}

// ---------------------------------------------------------------------------
// GEMM: h[N, 64] = X[N, K] @ W[K, 64].  Epilogue:
//   - store h as fp16 into g_hh (only consumer is the gather in gat_csr)
//   - fused attention logits g_als/g_ald (shfl-reduce over the 16 tx lanes)
// ---------------------------------------------------------------------------
template <int K, bool FROM_SCRATCH>
__global__ void gemm_kernel(const float* __restrict__ Xin,
                            const float* __restrict__ W,
                            const float* __restrict__ a_src,
                            const float* __restrict__ a_dst, int N) {
    const float* __restrict__ X = FROM_SCRATCH ? (const float*)g_x1 : Xin;
    __shared__ float Ws [64 * 64];
    __shared__ float XsT[64 * 68];

    const int tid  = threadIdx.x;
    const int row0 = blockIdx.x * 64;
    const int tx = tid & 15;         // cols 4*tx..4*tx+3
    const int ty = tid >> 4;         // rows 4*ty..4*ty+3
    const int KQ = K / 4;

    float acc[4][4] = {};

    for (int k0 = 0; k0 < K; k0 += 64) {
        for (int i = tid; i < 64 * 16; i += 256) {
            int kk = i / 16, cq = i % 16;
            ((float4*)Ws)[kk * 16 + cq] =
                ((const float4*)W)[(k0 + kk) * 16 + cq];
        }
        for (int i = tid; i < 64 * 16; i += 256) {
            int r = i / 16, kq = i % 16;
            float4 v = make_float4(0.f, 0.f, 0.f, 0.f);
            int gr = row0 + r;
            if (gr < N) v = ((const float4*)X)[gr * KQ + k0 / 4 + kq];
            XsT[(4 * kq + 0) * 68 + r] = v.x;
            XsT[(4 * kq + 1) * 68 + r] = v.y;
            XsT[(4 * kq + 2) * 68 + r] = v.z;
            XsT[(4 * kq + 3) * 68 + r] = v.w;
        }
        __syncthreads();

#pragma unroll 8
        for (int kk = 0; kk < 64; kk++) {
            float4 xv = *(const float4*)&XsT[kk * 68 + 4 * ty];
            float4 wv = *(const float4*)&Ws [kk * 64 + 4 * tx];
            float xr[4] = {xv.x, xv.y, xv.z, xv.w};
            float wc[4] = {wv.x, wv.y, wv.z, wv.w};
#pragma unroll
            for (int r = 0; r < 4; r++)
#pragma unroll
                for (int c = 0; c < 4; c++)
                    acc[r][c] = fmaf(xr[r], wc[c], acc[r][c]);
        }
        __syncthreads();
    }

    float4 avs = *(const float4*)&a_src[4 * tx];
    float4 avd = *(const float4*)&a_dst[4 * tx];

#pragma unroll
    for (int r = 0; r < 4; r++) {
        int gr = row0 + 4 * ty + r;
        float ps = acc[r][0] * avs.x + acc[r][1] * avs.y
                 + acc[r][2] * avs.z + acc[r][3] * avs.w;
        float pd = acc[r][0] * avd.x + acc[r][1] * avd.y
                 + acc[r][2] * avd.z + acc[r][3] * avd.w;
#pragma unroll
        for (int o = 8; o > 0; o >>= 1) {
            ps += __shfl_xor_sync(0xFFFFFFFFu, ps, o);
            pd += __shfl_xor_sync(0xFFFFFFFFu, pd, o);
        }
        if (gr < N) {
            __half2 p0 = __floats2half2_rn(acc[r][0], acc[r][1]);
            __half2 p1 = __floats2half2_rn(acc[r][2], acc[r][3]);
            *(__half2*)&g_hh[gr * HID + 4 * tx]     = p0;
            *(__half2*)&g_hh[gr * HID + 4 * tx + 2] = p1;
            if (tx == 0) {
                g_als[gr] = ps;
                g_ald[gr] = pd;
            }
        }
    }
}

// ---------------------------------------------------------------------------
// Fused single-pass GAT aggregation over CSR. One warp per dst node.
// h gathered in fp16 (half the L2 traffic), accumulated in fp32.
// Softmax shift is omitted (shift-invariant; logits are O(10)).
// ---------------------------------------------------------------------------
__global__ void gat_csr(const float* __restrict__ b, int N) {
    int gid  = blockIdx.x * blockDim.x + threadIdx.x;
    int node = gid >> 5;
    int lane = gid & 31;
    if (node >= N) return;

    int row0 = g_rptr[node];
    int deg  = g_deg[node];

    float ald_d = g_ald[node];
    float e_self = g_als[node] + ald_d;
    e_self = (e_self > 0.f) ? e_self : 0.2f * e_self;
    float w_self = __expf(e_self);

    float2 hv = __half22float2(*(const __half2*)&g_hh[node * HID + 2 * lane]);
    float ax = w_self * hv.x;
    float ay = w_self * hv.y;
    float wpart = 0.f;

    for (int c0 = 0; c0 < deg; c0 += 32) {
        int j = c0 + lane;
        int   s = 0;
        float w = 0.f;
        if (j < deg) {
            s = g_csrc[row0 + j];
            float e = g_als[s] + ald_d;
            e = (e > 0.f) ? e : 0.2f * e;
            w = __expf(e);
        }
        wpart += w;
        int kmax = min(32, deg - c0);
#pragma unroll 4
        for (int k = 0; k < kmax; k++) {
            float wk = __shfl_sync(0xFFFFFFFFu, w, k);
            int   sk = __shfl_sync(0xFFFFFFFFu, s, k);
            float2 hk = __half22float2(
                *(const __half2*)&g_hh[sk * HID + 2 * lane]);
            ax = fmaf(wk, hk.x, ax);
            ay = fmaf(wk, hk.y, ay);
        }
    }

#pragma unroll
    for (int o = 16; o > 0; o >>= 1)
        wpart += __shfl_xor_sync(0xFFFFFFFFu, wpart, o);
    float inv = __fdividef(1.f, wpart + w_self);

    float2 bb = *(const float2*)&b[2 * lane];
    float vx = ax * inv + bb.x;
    float vy = ay * inv + bb.y;
    vx = (vx > 0.f) ? vx : expm1f(vx);
    vy = (vy > 0.f) ? vy : expm1f(vy);
    *(float2*)&g_x1[node * HID + 2 * lane] = make_float2(vx, vy);
}

// ---------------------------------------------------------------------------
// Pooling + FC
// ---------------------------------------------------------------------------
__global__ void pool_zero(int G) {
    int i = blockIdx.x * blockDim.x + threadIdx.x;
    if (i < G * HID) g_pool[i] = 0.f;
    if (i < G)       g_cnt[i]  = 0;
}

__global__ void pool_acc(const int* __restrict__ batch, int N) {
    int gid  = blockIdx.x * blockDim.x + threadIdx.x;
    int node = gid >> 4;
    int sl   = gid & 15;
    if (node >= N) return;
    int g = batch[node];
    float4 v = *(const float4*)&g_x1[node * HID + sl * 4];
    red_add_v4(&g_pool[g * HID + sl * 4], v);
    if (sl == 0) atomicAdd(&g_cnt[g], 1);
}

__global__ void final_fc(const float* __restrict__ Wfc,
                         const float* __restrict__ bfc,
                         float* __restrict__ out, int G) {
    int g = blockIdx.x * blockDim.x + threadIdx.x;
    if (g >= G) return;
    float acc = 0.f;
#pragma unroll 8
    for (int c = 0; c < HID; c++)
        acc += g_pool[g * HID + c] * Wfc[c];
    float n = (float)(g_cnt[g] > 0 ? g_cnt[g] : 1);
    out[g] = acc / n + bfc[0];
}

// ---------------------------------------------------------------------------
// Launch
// ---------------------------------------------------------------------------
extern "C" void kernel_launch(void* const* d_in, const int* in_sizes, int n_in,
                              void* d_out, int out_size) {
    const float* x     = (const float*)d_in[0];
    const int*   ei    = (const int*)d_in[1];
    const int*   batch = (const int*)d_in[2];
    const float* W1  = (const float*)d_in[3];
    const float* as1 = (const float*)d_in[4];
    const float* ad1 = (const float*)d_in[5];
    const float* b1  = (const float*)d_in[6];
    const float* W2  = (const float*)d_in[7];
    const float* as2 = (const float*)d_in[8];
    const float* ad2 = (const float*)d_in[9];
    const float* b2  = (const float*)d_in[10];
    const float* Wfc = (const float*)d_in[11];
    const float* bfc = (const float*)d_in[12];
    float* out = (float*)d_out;

    const int hid = in_sizes[4];            // 64
    const int IN  = in_sizes[3] / hid;      // 128
    const int N   = in_sizes[0] / IN;       // 100000
    const int E   = in_sizes[1] / 2;        // 1600000
    const int G   = out_size;               // 256

    const int gb     = (N + 63) / 64;
    const int nwarps = (N * 32 + 255) / 256;
    const int npool  = (N * 16 + 255) / 256;
    const int eb4    = ((E + 3) / 4 + 255) / 256;
    const int nb256  = (N + 255) / 256;

    // ---- CSR build (shared by both layers) ----
    deg_zero<<<nb256, 256>>>(N);
    deg_count<<<eb4, 256>>>(ei, E);
    row_alloc<<<nb256, 256>>>(N);
    csr_fill<<<eb4, 256>>>(ei, E);

    // ---- layer 1 ----
    gemm_kernel<128, false><<<gb, 256>>>(x, W1, as1, ad1, N);
    gat_csr<<<nwarps, 256>>>(b1, N);

    // ---- layer 2 ----
    gemm_kernel<64, true><<<gb, 256>>>(x, W2, as2, ad2, N);
    gat_csr<<<nwarps, 256>>>(b2, N);

    // ---- pool + fc ----
    pool_zero<<<(G * HID + 255) / 256, 256>>>(G);
    pool_acc<<<npool, 256>>>(batch, N);
    final_fc<<<(G + 255) / 256, 256>>>(Wfc, bfc, out, G);
}

// round 8
// speedup vs baseline: 2.5161x; 1.0537x over previous
#include <cuda_runtime.h>
#include <cuda_fp16.h>
#include <mma.h>

using namespace nvcuda;

// ---------------------------------------------------------------------------
// Scratch (static __device__ — no allocations allowed anywhere)
// ---------------------------------------------------------------------------
#define NMAX   100096
#define EMAX   1605632
#define HID    64

__device__ __align__(16) __half g_hh [NMAX * HID];  // h (fp16 gather copy)
__device__ __align__(16) float  g_x1 [NMAX * HID];  // layer output / next input
__device__ __align__(16) float  g_als[NMAX];
__device__ __align__(16) float  g_ald[NMAX];
__device__               int    g_deg [NMAX];
__device__               int    g_rptr[NMAX];
__device__               int    g_cur [NMAX];
__device__               int    g_csrc[EMAX];
__device__               int    g_total;
__device__ __align__(16) float  g_pool[256 * HID];
__device__               int    g_cnt [256];

__device__ __forceinline__ void red_add_v4(float* addr, float4 v) {
    asm volatile("red.global.add.v4.f32 [%0], {%1, %2, %3, %4};"
                 :: "l"(addr), "f"(v.x), "f"(v.y), "f"(v.z), "f"(v.w)
                 : "memory");
}

// load 4 consecutive halves as float4
__device__ __forceinline__ float4 ld4h(const __half* p) {
    uint2 u = *(const uint2*)p;
    __half2 h0 = *(__half2*)&u.x;
    __half2 h1 = *(__half2*)&u.y;
    float2 f0 = __half22float2(h0);
    float2 f1 = __half22float2(h1);
    return make_float4(f0.x, f0.y, f1.x, f1.y);
}

// ---------------------------------------------------------------------------
// CSR build
// ---------------------------------------------------------------------------
__global__ void deg_zero(int N) {
    int i = blockIdx.x * blockDim.x + threadIdx.x;
    if (i < N) g_deg[i] = 0;
    if (i == 0) g_total = 0;
}

__global__ void deg_count(const int* __restrict__ ei, int E) {
    int t = blockIdx.x * blockDim.x + threadIdx.x;
    int base = 4 * t;
    if (base + 3 < E) {
        int4 d4 = *(const int4*)&ei[E + base];
        atomicAdd(&g_deg[d4.x], 1);
        atomicAdd(&g_deg[d4.y], 1);
        atomicAdd(&g_deg[d4.z], 1);
        atomicAdd(&g_deg[d4.w], 1);
    } else {
        for (int j = base; j < E && j < base + 4; j++)
            atomicAdd(&g_deg[ei[E + j]], 1);
    }
}

__global__ void row_alloc(int N) {
    int i = blockIdx.x * blockDim.x + threadIdx.x;
    if (i >= N) return;
    int d = g_deg[i];
    int r = d ? atomicAdd(&g_total, d) : 0;
    g_rptr[i] = r;
    g_cur[i]  = r;
}

__global__ void csr_fill(const int* __restrict__ ei, int E) {
    int t = blockIdx.x * blockDim.x + threadIdx.x;
    int base = 4 * t;
    if (base + 3 < E) {
        int4 s4 = *(const int4*)&ei[base];
        int4 d4 = *(const int4*)&ei[E + base];
        int p0 = atomicAdd(&g_cur[d4.x], 1);
        int p1 = atomicAdd(&g_cur[d4.y], 1);
        int p2 = atomicAdd(&g_cur[d4.z], 1);
        int p3 = atomicAdd(&g_cur[d4.w], 1);
        g_csrc[p0] = s4.x;
        g_csrc[p1] = s4.y;
        g_csrc[p2] = s4.z;
        g_csrc[p3] = s4.w;
    } else {
        for (int j = base; j < E && j < base + 4; j++) {
            int pos = atomicAdd(&g_cur[ei[E + j]], 1);
            g_csrc[pos] = ei[j];
        }
    }
}

// ---------------------------------------------------------------------------
// Tensor-core GEMM (wmma fp16 x fp16 -> fp32): h[N,64] = X[N,K] @ W[K,64]
// Block = 256 threads (8 warps), 64x64 output tile.
// Warp w: rows 16*(w>>1), cols 32*(w&1); 2 wmma acc frags; K loop in 16s.
// Epilogue: fp32 accum -> smem Cs; fused logits (als/ald); h stored fp16.
// ---------------------------------------------------------------------------
template <int K, bool FROM_SCRATCH>
__global__ void gemm_kernel(const float* __restrict__ Xin,
                            const float* __restrict__ W,
                            const float* __restrict__ a_src,
                            const float* __restrict__ a_dst, int N) {
    const float* __restrict__ X = FROM_SCRATCH ? (const float*)g_x1 : Xin;

    constexpr int LDA = K + 8;                       // halves per As row
    constexpr int AB_BYTES = (64 * LDA + K * 64) * 2;
    constexpr int C_BYTES  = 64 * 68 * 4;
    constexpr int SM_BYTES = AB_BYTES > C_BYTES ? AB_BYTES : C_BYTES;
    __shared__ __align__(16) char smbuf[SM_BYTES];

    __half* As = (__half*)smbuf;                     // [64][LDA]
    __half* Bs = As + 64 * LDA;                      // [K][64]
    float*  Cs = (float*)smbuf;                      // [64][68] (aliases A/B)

    const int tid  = threadIdx.x;
    const int row0 = blockIdx.x * 64;
    const int lane = tid & 31;
    const int w    = tid >> 5;
    const int KQ   = K / 4;

    // stage X tile (fp32 -> fp16)
    for (int i = tid; i < 64 * KQ; i += 256) {
        int r = i / KQ, kq = i % KQ;
        float4 v = make_float4(0.f, 0.f, 0.f, 0.f);
        int gr = row0 + r;
        if (gr < N) v = ((const float4*)X)[gr * KQ + kq];
        *(__half2*)&As[r * LDA + 4 * kq]     = __floats2half2_rn(v.x, v.y);
        *(__half2*)&As[r * LDA + 4 * kq + 2] = __floats2half2_rn(v.z, v.w);
    }
    // stage W (fp32 -> fp16), row-major [K][64]
    for (int i = tid; i < K * 16; i += 256) {
        int kk = i / 16, cq = i % 16;
        float4 v = ((const float4*)W)[kk * 16 + cq];
        *(__half2*)&Bs[kk * 64 + 4 * cq]     = __floats2half2_rn(v.x, v.y);
        *(__half2*)&Bs[kk * 64 + 4 * cq + 2] = __floats2half2_rn(v.z, v.w);
    }
    __syncthreads();

    const int wr = w >> 1;      // 0..3 : rows 16*wr
    const int wc = w & 1;       // 0..1 : cols 32*wc

    wmma::fragment<wmma::accumulator, 16, 16, 16, float> c0, c1;
    wmma::fill_fragment(c0, 0.f);
    wmma::fill_fragment(c1, 0.f);

#pragma unroll
    for (int k0 = 0; k0 < K; k0 += 16) {
        wmma::fragment<wmma::matrix_a, 16, 16, 16, __half, wmma::row_major> a;
        wmma::fragment<wmma::matrix_b, 16, 16, 16, __half, wmma::row_major> b0, b1;
        wmma::load_matrix_sync(a,  As + wr * 16 * LDA + k0, LDA);
        wmma::load_matrix_sync(b0, Bs + k0 * 64 + wc * 32, 64);
        wmma::load_matrix_sync(b1, Bs + k0 * 64 + wc * 32 + 16, 64);
        wmma::mma_sync(c0, a, b0, c0);
        wmma::mma_sync(c1, a, b1, c1);
    }
    __syncthreads();   // done reading As/Bs before aliasing as Cs

    wmma::store_matrix_sync(Cs + wr * 16 * 68 + wc * 32,      c0, 68,
                            wmma::mem_row_major);
    wmma::store_matrix_sync(Cs + wr * 16 * 68 + wc * 32 + 16, c1, 68,
                            wmma::mem_row_major);
    __syncthreads();

    // fused logits: warp w handles rows 8w..8w+7
    {
        float as1 = a_src[lane], as2 = a_src[lane + 32];
        float ad1 = a_dst[lane], ad2 = a_dst[lane + 32];
#pragma unroll
        for (int rr = 0; rr < 8; rr++) {
            int r  = w * 8 + rr;
            int gr = row0 + r;
            float v1 = Cs[r * 68 + lane];
            float v2 = Cs[r * 68 + lane + 32];
            float ps = v1 * as1 + v2 * as2;
            float pd = v1 * ad1 + v2 * ad2;
#pragma unroll
            for (int o = 16; o > 0; o >>= 1) {
                ps += __shfl_xor_sync(0xFFFFFFFFu, ps, o);
                pd += __shfl_xor_sync(0xFFFFFFFFu, pd, o);
            }
            if (lane == 0 && gr < N) {
                g_als[gr] = ps;
                g_ald[gr] = pd;
            }
        }
    }

    // h store (fp32 Cs -> fp16 g_hh): thread -> row tid>>2, 16-col chunk
    {
        int r  = tid >> 2;
        int c0b = (tid & 3) * 16;
        int gr = row0 + r;
        if (gr < N) {
#pragma unroll
            for (int c = 0; c < 16; c += 4) {
                float4 v = *(const float4*)&Cs[r * 68 + c0b + c];
                *(__half2*)&g_hh[gr * HID + c0b + c]     = __floats2half2_rn(v.x, v.y);
                *(__half2*)&g_hh[gr * HID + c0b + c + 2] = __floats2half2_rn(v.z, v.w);
            }
        }
    }
}

// ---------------------------------------------------------------------------
// Fused single-pass GAT aggregation over CSR. One warp per dst node.
// Two edges per broadcast step: half-warp (16 lanes x 4 cols) per edge;
// partials merged with shfl_xor(16) at the end. h gathered fp16, accum fp32.
// ---------------------------------------------------------------------------
__global__ void gat_csr(const float* __restrict__ b, int N) {
    int gid  = blockIdx.x * blockDim.x + threadIdx.x;
    int node = gid >> 5;
    int lane = gid & 31;
    if (node >= N) return;

    int row0 = g_rptr[node];
    int deg  = g_deg[node];
    int grp  = lane >> 4;       // which edge of the pair
    int cl   = lane & 15;       // column group: cols 4*cl .. 4*cl+3

    float ald_d = g_ald[node];
    float e_self = g_als[node] + ald_d;
    e_self = (e_self > 0.f) ? e_self : 0.2f * e_self;
    float w_self = __expf(e_self);

    float4 acc = make_float4(0.f, 0.f, 0.f, 0.f);
    if (grp == 0) {
        float4 hv = ld4h(&g_hh[node * HID + 4 * cl]);
        acc.x = w_self * hv.x; acc.y = w_self * hv.y;
        acc.z = w_self * hv.z; acc.w = w_self * hv.w;
    }
    float wpart = 0.f;

    for (int c0 = 0; c0 < deg; c0 += 32) {
        int j = c0 + lane;
        int   s = 0;
        float w = 0.f;
        if (j < deg) {
            s = g_csrc[row0 + j];
            float e = g_als[s] + ald_d;
            e = (e > 0.f) ? e : 0.2f * e;
            w = __expf(e);
        }
        wpart += w;
        int kmax = min(32, deg - c0);
#pragma unroll 2
        for (int k = 0; k < kmax; k += 2) {
            int ksel = k + grp;
            float wk = __shfl_sync(0xFFFFFFFFu, w, ksel & 31);
            int   sk = __shfl_sync(0xFFFFFFFFu, s, ksel & 31);
            if (ksel < kmax) {
                float4 hk = ld4h(&g_hh[sk * HID + 4 * cl]);
                acc.x = fmaf(wk, hk.x, acc.x);
                acc.y = fmaf(wk, hk.y, acc.y);
                acc.z = fmaf(wk, hk.z, acc.z);
                acc.w = fmaf(wk, hk.w, acc.w);
            }
        }
    }

    // merge the two half-warp partials (same columns, complementary edges)
    acc.x += __shfl_xor_sync(0xFFFFFFFFu, acc.x, 16);
    acc.y += __shfl_xor_sync(0xFFFFFFFFu, acc.y, 16);
    acc.z += __shfl_xor_sync(0xFFFFFFFFu, acc.z, 16);
    acc.w += __shfl_xor_sync(0xFFFFFFFFu, acc.w, 16);

#pragma unroll
    for (int o = 16; o > 0; o >>= 1)
        wpart += __shfl_xor_sync(0xFFFFFFFFu, wpart, o);
    float inv = __fdividef(1.f, wpart + w_self);

    if (grp == 0) {
        float4 bb = *(const float4*)&b[4 * cl];
        float4 r;
        r.x = acc.x * inv + bb.x;
        r.y = acc.y * inv + bb.y;
        r.z = acc.z * inv + bb.z;
        r.w = acc.w * inv + bb.w;
        r.x = (r.x > 0.f) ? r.x : expm1f(r.x);
        r.y = (r.y > 0.f) ? r.y : expm1f(r.y);
        r.z = (r.z > 0.f) ? r.z : expm1f(r.z);
        r.w = (r.w > 0.f) ? r.w : expm1f(r.w);
        *(float4*)&g_x1[node * HID + 4 * cl] = r;
    }
}

// ---------------------------------------------------------------------------
// Pooling + FC
// ---------------------------------------------------------------------------
__global__ void pool_zero(int G) {
    int i = blockIdx.x * blockDim.x + threadIdx.x;
    if (i < G * HID) g_pool[i] = 0.f;
    if (i < G)       g_cnt[i]  = 0;
}

__global__ void pool_acc(const int* __restrict__ batch, int N) {
    int gid  = blockIdx.x * blockDim.x + threadIdx.x;
    int node = gid >> 4;
    int sl   = gid & 15;
    if (node >= N) return;
    int g = batch[node];
    float4 v = *(const float4*)&g_x1[node * HID + sl * 4];
    red_add_v4(&g_pool[g * HID + sl * 4], v);
    if (sl == 0) atomicAdd(&g_cnt[g], 1);
}

__global__ void final_fc(const float* __restrict__ Wfc,
                         const float* __restrict__ bfc,
                         float* __restrict__ out, int G) {
    int g = blockIdx.x * blockDim.x + threadIdx.x;
    if (g >= G) return;
    float acc = 0.f;
#pragma unroll 8
    for (int c = 0; c < HID; c++)
        acc += g_pool[g * HID + c] * Wfc[c];
    float n = (float)(g_cnt[g] > 0 ? g_cnt[g] : 1);
    out[g] = acc / n + bfc[0];
}

// ---------------------------------------------------------------------------
// Launch
// ---------------------------------------------------------------------------
extern "C" void kernel_launch(void* const* d_in, const int* in_sizes, int n_in,
                              void* d_out, int out_size) {
    const float* x     = (const float*)d_in[0];
    const int*   ei    = (const int*)d_in[1];
    const int*   batch = (const int*)d_in[2];
    const float* W1  = (const float*)d_in[3];
    const float* as1 = (const float*)d_in[4];
    const float* ad1 = (const float*)d_in[5];
    const float* b1  = (const float*)d_in[6];
    const float* W2  = (const float*)d_in[7];
    const float* as2 = (const float*)d_in[8];
    const float* ad2 = (const float*)d_in[9];
    const float* b2  = (const float*)d_in[10];
    const float* Wfc = (const float*)d_in[11];
    const float* bfc = (const float*)d_in[12];
    float* out = (float*)d_out;

    const int hid = in_sizes[4];            // 64
    const int IN  = in_sizes[3] / hid;      // 128
    const int N   = in_sizes[0] / IN;       // 100000
    const int E   = in_sizes[1] / 2;        // 1600000
    const int G   = out_size;               // 256

    const int gb     = (N + 63) / 64;
    const int nwarps = (N * 32 + 255) / 256;
    const int npool  = (N * 16 + 255) / 256;
    const int eb4    = ((E + 3) / 4 + 255) / 256;
    const int nb256  = (N + 255) / 256;

    // ---- CSR build (shared by both layers) ----
    deg_zero<<<nb256, 256>>>(N);
    deg_count<<<eb4, 256>>>(ei, E);
    row_alloc<<<nb256, 256>>>(N);
    csr_fill<<<eb4, 256>>>(ei, E);

    // ---- layer 1 ----
    gemm_kernel<128, false><<<gb, 256>>>(x, W1, as1, ad1, N);
    gat_csr<<<nwarps, 256>>>(b1, N);

    // ---- layer 2 ----
    gemm_kernel<64, true><<<gb, 256>>>(x, W2, as2, ad2, N);
    gat_csr<<<nwarps, 256>>>(b2, N);

    // ---- pool + fc ----
    pool_zero<<<(G * HID + 255) / 256, 256>>>(G);
    pool_acc<<<npool, 256>>>(batch, N);
    final_fc<<<(G + 255) / 256, 256>>>(Wfc, bfc, out, G);
}